// round 10
// baseline (speedup 1.0000x reference)
#include <cuda_runtime.h>
#include <cuda_bf16.h>

#define NQ 4
#define NL 2
#define NT 256
#define SPB (2 * NT)   // samples per block

typedef unsigned long long ull;

__device__ float d_T[108];  // 27 float4 rows: T[w0*9+w1*3+w2][w3], pad=0

__device__ __forceinline__ ull pack2(float lo, float hi) {
    ull r; asm("mov.b64 %0, {%1, %2};" : "=l"(r) : "f"(lo), "f"(hi)); return r;
}
__device__ __forceinline__ ull dup2(float x) { return pack2(x, x); }
__device__ __forceinline__ void unpack2(ull v, float& lo, float& hi) {
    asm("mov.b64 {%0, %1}, %2;" : "=f"(lo), "=f"(hi) : "l"(v));
}
__device__ __forceinline__ ull ffma2(ull a, ull b, ull c) {
    ull d; asm("fma.rn.f32x2 %0, %1, %2, %3;" : "=l"(d) : "l"(a), "l"(b), "l"(c)); return d;
}

__device__ __forceinline__ float2 cmul(float2 a, float2 b) {
    return make_float2(a.x * b.x - a.y * b.y, a.x * b.y + a.y * b.x);
}
__device__ __forceinline__ float2 cadd(float2 a, float2 b) {
    return make_float2(a.x + b.x, a.y + b.y);
}

// m(a,b,w): contribution of psi-pair bits (a,b) on one qubit to basis w (1,cos,sin)
__device__ __forceinline__ float mcoef(int a, int b, int w) {
    if (w == 0) return (a == b) ? 0.5f : 0.f;
    if (w == 1) return (a == b) ? (a ? -0.5f : 0.5f) : 0.f;
    return (a != b) ? 0.5f : 0.f;
}

// Build fixed circuit unitary U from qweights, A = Re(U^dag Z0 U), then the
// 81-coeff trig tensor T[w] = sum_{j,k} A[j][k] prod_i mcoef(j_i,k_i,w_i).
__global__ void qnn_setup_kernel(const float* __restrict__ qw) {
    __shared__ float2 U[16][16];
    __shared__ float sA[256];
    int t = threadIdx.x;  // 256 threads
    {
        int r = t >> 4, c = t & 15;
        U[r][c] = make_float2(r == c ? 1.f : 0.f, 0.f);
    }
    __syncthreads();

    for (int l = 0; l < NL; l++) {
        for (int i = 0; i < NQ; i++) {
            float phi = qw[(l * NQ + i) * 3 + 0];
            float th  = qw[(l * NQ + i) * 3 + 1];
            float om  = qw[(l * NQ + i) * 3 + 2];
            float ct = cosf(0.5f * th), st = sinf(0.5f * th);
            float ap = 0.5f * (phi + om), am = 0.5f * (phi - om);
            float cap = cosf(ap), sap = sinf(ap);
            float cam = cosf(am), sam = sinf(am);
            float2 g00 = make_float2( cap * ct, -sap * ct);
            float2 g01 = make_float2(-cam * st, -sam * st);
            float2 g10 = make_float2( cam * st, -sam * st);
            float2 g11 = make_float2( cap * ct,  sap * ct);
            int bit = 3 - i;
            if (t < 128) {
                int pair = t >> 4;
                int c = t & 15;
                int low = pair & ((1 << bit) - 1);
                int hi  = pair >> bit;
                int r0  = (hi << (bit + 1)) | low;
                int r1  = r0 | (1 << bit);
                float2 u0 = U[r0][c], u1 = U[r1][c];
                U[r0][c] = cadd(cmul(g00, u0), cmul(g01, u1));
                U[r1][c] = cadd(cmul(g10, u0), cmul(g11, u1));
            }
            __syncthreads();
        }
        {
            int r = t >> 4, c = t & 15;
            float sign = 1.f;
            if (((r >> 3) & 1) && ((r >> 2) & 1)) sign = -sign;
            if (((r >> 2) & 1) && ((r >> 1) & 1)) sign = -sign;
            if (((r >> 1) & 1) && (r & 1))        sign = -sign;
            U[r][c].x *= sign;
            U[r][c].y *= sign;
        }
        __syncthreads();
    }

    // A[j][k] = sum_r z(r) * Re(conj(U[r][j]) * U[r][k])
    {
        int j = t >> 4, k = t & 15;
        float acc = 0.f;
        #pragma unroll
        for (int r = 0; r < 16; r++) {
            float z = (r & 8) ? -1.f : 1.f;
            acc += z * (U[r][j].x * U[r][k].x + U[r][j].y * U[r][k].y);
        }
        sA[j * 16 + k] = acc;
    }
    __syncthreads();

    // T coefficients (81 of them); qubit i -> bit (3-i)
    if (t < 81) {
        int w0 = t / 27, w1 = (t / 9) % 3, w2 = (t / 3) % 3, w3 = t % 3;
        float sum = 0.f;
        for (int j = 0; j < 16; j++) {
            int j0 = (j >> 3) & 1, j1 = (j >> 2) & 1, j2 = (j >> 1) & 1, j3 = j & 1;
            for (int k = 0; k < 16; k++) {
                int k0 = (k >> 3) & 1, k1 = (k >> 2) & 1, k2 = (k >> 1) & 1, k3 = k & 1;
                float c = mcoef(j0, k0, w0) * mcoef(j1, k1, w1)
                        * mcoef(j2, k2, w2) * mcoef(j3, k3, w3);
                if (c != 0.f) sum += sA[j * 16 + k] * c;
            }
        }
        d_T[(t / 3) * 4 + w3] = sum;   // row = w0*9+w1*3+w2, comp = w3
    }
    if (t < 27) d_T[t * 4 + 3] = 0.f;  // pad
}

__global__ __launch_bounds__(NT, 2) void qnn_main_kernel(
    const float* __restrict__ text, const float* __restrict__ image,
    const float* __restrict__ tW1, const float* __restrict__ tb1,
    const float* __restrict__ tW2, const float* __restrict__ tb2,
    const float* __restrict__ iW1, const float* __restrict__ ib1,
    const float* __restrict__ iW2, const float* __restrict__ ib2,
    const float* __restrict__ cW1, const float* __restrict__ cb1,
    const float* __restrict__ cW2, const float* __restrict__ cb2,
    float* __restrict__ out)
{
    __shared__ __align__(16) float s_tW1[16 * 32];
    __shared__ __align__(16) float s_tb1[32];
    __shared__ __align__(16) float s_tW2[32 * 4];
    __shared__ __align__(16) float s_iW1[48 * 64];
    __shared__ __align__(16) float s_ib1[64];
    __shared__ __align__(16) float s_iW2[64 * 4];
    __shared__ __align__(16) float s_T[108];
    __shared__ float s_tb2[4], s_ib2[4];
    __shared__ float s_cW1[16], s_cb1[16], s_cW2[32], s_cb2[2];

    int tid = threadIdx.x;
    for (int i = tid; i < 512; i += NT) s_tW1[i] = tW1[i];
    for (int i = tid; i < 3072; i += NT) s_iW1[i] = iW1[i];
    for (int i = tid; i < 256; i += NT) s_iW2[i] = iW2[i];
    for (int i = tid; i < 128; i += NT) s_tW2[i] = tW2[i];
    if (tid < 108) s_T[tid] = d_T[tid];
    if (tid < 64) s_ib1[tid] = ib1[tid];
    if (tid < 32) { s_tb1[tid] = tb1[tid]; s_cW2[tid] = cW2[tid]; }
    if (tid < 16) { s_cW1[tid] = cW1[tid]; s_cb1[tid] = cb1[tid]; }
    if (tid < 4) { s_tb2[tid] = tb2[tid]; s_ib2[tid] = ib2[tid]; }
    if (tid < 2) s_cb2[tid] = cb2[tid];
    __syncthreads();

    int b0 = blockIdx.x * SPB + tid;       // sample 0
    int b1 = b0 + NT;                      // sample 1

    float fb0 = s_tb2[0] + s_ib2[0];
    float fb1 = s_tb2[1] + s_ib2[1];
    float fb2 = s_tb2[2] + s_ib2[2];
    float fb3 = s_tb2[3] + s_ib2[3];
    float a00 = fb0, a01 = fb1, a02 = fb2, a03 = fb3;   // feats sample 0
    float a10 = fb0, a11 = fb1, a12 = fb2, a13 = fb3;   // feats sample 1

    // ---- text MLP: 16 -> 32 (relu) -> 4; 2 samples, 2 j-passes of 16 ----
    {
        float tx0[16], tx1[16];
        {
            const float4* p0 = (const float4*)(text + (size_t)b0 * 16);
            const float4* p1 = (const float4*)(text + (size_t)b1 * 16);
            #pragma unroll
            for (int k4 = 0; k4 < 4; k4++) {
                float4 v0 = p0[k4], v1 = p1[k4];
                tx0[4*k4+0] = v0.x; tx0[4*k4+1] = v0.y; tx0[4*k4+2] = v0.z; tx0[4*k4+3] = v0.w;
                tx1[4*k4+0] = v1.x; tx1[4*k4+1] = v1.y; tx1[4*k4+2] = v1.z; tx1[4*k4+3] = v1.w;
            }
        }
        #pragma unroll
        for (int jt = 0; jt < 2; jt++) {
            ull h0[8], h1[8];   // 16 hidden each
            {
                const ulonglong2* bb = (const ulonglong2*)&s_tb1[jt * 16];
                #pragma unroll
                for (int p = 0; p < 4; p++) {
                    ulonglong2 v = bb[p];
                    h0[2*p] = v.x; h0[2*p+1] = v.y;
                    h1[2*p] = v.x; h1[2*p+1] = v.y;
                }
            }
            #pragma unroll
            for (int k = 0; k < 16; k++) {
                ull xd0 = dup2(tx0[k]);
                ull xd1 = dup2(tx1[k]);
                const ulonglong2* wrow = (const ulonglong2*)&s_tW1[k * 32 + jt * 16];
                #pragma unroll
                for (int p = 0; p < 4; p++) {
                    ulonglong2 w = wrow[p];
                    h0[2*p]   = ffma2(xd0, w.x, h0[2*p]);
                    h0[2*p+1] = ffma2(xd0, w.y, h0[2*p+1]);
                    h1[2*p]   = ffma2(xd1, w.x, h1[2*p]);
                    h1[2*p+1] = ffma2(xd1, w.y, h1[2*p+1]);
                }
            }
            // second layer rows [jt*16, jt*16+16)
            #pragma unroll
            for (int m = 0; m < 8; m++) {
                int r = jt * 16 + 2 * m;
                float4 w0 = *(const float4*)&s_tW2[r * 4];
                float4 w1 = *(const float4*)&s_tW2[(r + 1) * 4];
                float ha0, hb0, ha1, hb1;
                unpack2(h0[m], ha0, hb0); unpack2(h1[m], ha1, hb1);
                ha0 = fmaxf(ha0, 0.f); hb0 = fmaxf(hb0, 0.f);
                ha1 = fmaxf(ha1, 0.f); hb1 = fmaxf(hb1, 0.f);
                a00 = fmaf(ha0, w0.x, a00); a01 = fmaf(ha0, w0.y, a01);
                a02 = fmaf(ha0, w0.z, a02); a03 = fmaf(ha0, w0.w, a03);
                a00 = fmaf(hb0, w1.x, a00); a01 = fmaf(hb0, w1.y, a01);
                a02 = fmaf(hb0, w1.z, a02); a03 = fmaf(hb0, w1.w, a03);
                a10 = fmaf(ha1, w0.x, a10); a11 = fmaf(ha1, w0.y, a11);
                a12 = fmaf(ha1, w0.z, a12); a13 = fmaf(ha1, w0.w, a13);
                a10 = fmaf(hb1, w1.x, a10); a11 = fmaf(hb1, w1.y, a11);
                a12 = fmaf(hb1, w1.z, a12); a13 = fmaf(hb1, w1.w, a13);
            }
        }
    }

    // ---- image MLP: 48 -> 64 (relu) -> 4; 2 samples, 2 j-passes of 32 ----
    {
        const float4* p0 = (const float4*)(image + (size_t)b0 * 48);
        const float4* p1 = (const float4*)(image + (size_t)b1 * 48);
        #pragma unroll
        for (int jt = 0; jt < 2; jt++) {
            ull h0[16], h1[16];   // 32 hidden each
            {
                const ulonglong2* bb = (const ulonglong2*)&s_ib1[jt * 32];
                #pragma unroll
                for (int p = 0; p < 8; p++) {
                    ulonglong2 v = bb[p];
                    h0[2*p] = v.x; h0[2*p+1] = v.y;
                    h1[2*p] = v.x; h1[2*p+1] = v.y;
                }
            }
            #pragma unroll 4
            for (int kb = 0; kb < 12; kb++) {
                float4 v0 = p0[kb];   // gmem (L1 hit on 2nd pass)
                float4 v1 = p1[kb];
                float xs0[4] = {v0.x, v0.y, v0.z, v0.w};
                float xs1[4] = {v1.x, v1.y, v1.z, v1.w};
                #pragma unroll
                for (int kk = 0; kk < 4; kk++) {
                    int k = 4 * kb + kk;
                    ull xd0 = dup2(xs0[kk]);
                    ull xd1 = dup2(xs1[kk]);
                    const ulonglong2* wrow = (const ulonglong2*)&s_iW1[k * 64 + jt * 32];
                    #pragma unroll
                    for (int p = 0; p < 8; p++) {
                        ulonglong2 w = wrow[p];
                        h0[2*p]   = ffma2(xd0, w.x, h0[2*p]);
                        h0[2*p+1] = ffma2(xd0, w.y, h0[2*p+1]);
                        h1[2*p]   = ffma2(xd1, w.x, h1[2*p]);
                        h1[2*p+1] = ffma2(xd1, w.y, h1[2*p+1]);
                    }
                }
            }
            // second layer rows [jt*32, jt*32+32)
            #pragma unroll
            for (int m = 0; m < 16; m++) {
                int r = jt * 32 + 2 * m;
                float4 w0 = *(const float4*)&s_iW2[r * 4];
                float4 w1 = *(const float4*)&s_iW2[(r + 1) * 4];
                float ha0, hb0, ha1, hb1;
                unpack2(h0[m], ha0, hb0); unpack2(h1[m], ha1, hb1);
                ha0 = fmaxf(ha0, 0.f); hb0 = fmaxf(hb0, 0.f);
                ha1 = fmaxf(ha1, 0.f); hb1 = fmaxf(hb1, 0.f);
                a00 = fmaf(ha0, w0.x, a00); a01 = fmaf(ha0, w0.y, a01);
                a02 = fmaf(ha0, w0.z, a02); a03 = fmaf(ha0, w0.w, a03);
                a00 = fmaf(hb0, w1.x, a00); a01 = fmaf(hb0, w1.y, a01);
                a02 = fmaf(hb0, w1.z, a02); a03 = fmaf(hb0, w1.w, a03);
                a10 = fmaf(ha1, w0.x, a10); a11 = fmaf(ha1, w0.y, a11);
                a12 = fmaf(ha1, w0.z, a12); a13 = fmaf(ha1, w0.w, a13);
                a10 = fmaf(hb1, w1.x, a10); a11 = fmaf(hb1, w1.y, a11);
                a12 = fmaf(hb1, w1.z, a12); a13 = fmaf(hb1, w1.w, a13);
            }
        }
    }

    // ---- quantum: f_i = 0.5*acc_i (FULL angle); q = T contraction ----
    // u_i = (1, cos f_i, sin f_i); q = sum T[w0w1w2w3] u0 u1 u2 u3
    float ca[4], sa[4], cb[4], sb[4];
    {
        float f0[4] = {0.5f * a00, 0.5f * a01, 0.5f * a02, 0.5f * a03};
        float f1[4] = {0.5f * a10, 0.5f * a11, 0.5f * a12, 0.5f * a13};
        #pragma unroll
        for (int i = 0; i < 4; i++) { __sincosf(f0[i], &sa[i], &ca[i]); __sincosf(f1[i], &sb[i], &cb[i]); }
    }
    float B0[9] = {1.f, ca[1], sa[1], ca[0], ca[0]*ca[1], ca[0]*sa[1], sa[0], sa[0]*ca[1], sa[0]*sa[1]};
    float B1[9] = {1.f, cb[1], sb[1], cb[0], cb[0]*cb[1], cb[0]*sb[1], sb[0], sb[0]*cb[1], sb[0]*sb[1]};

    float q0 = 0.f, q1 = 0.f;
    #pragma unroll
    for (int n = 0; n < 9; n++) {
        float s2a = 0.f, s2b = 0.f;
        #pragma unroll
        for (int w2 = 0; w2 < 3; w2++) {
            float4 tr = *(const float4*)&s_T[(n * 3 + w2) * 4];   // shared by both samples
            float da = fmaf(tr.z, sa[3], fmaf(tr.y, ca[3], tr.x));
            float db = fmaf(tr.z, sb[3], fmaf(tr.y, cb[3], tr.x));
            float u2a = (w2 == 0) ? 1.f : (w2 == 1) ? ca[2] : sa[2];
            float u2b = (w2 == 0) ? 1.f : (w2 == 1) ? cb[2] : sb[2];
            s2a = fmaf(u2a, da, s2a);
            s2b = fmaf(u2b, db, s2b);
        }
        q0 = fmaf(B0[n], s2a, q0);
        q1 = fmaf(B1[n], s2b, q1);
    }

    // ---- classifier: q -> 16 (relu) -> 2; shared weight loads ----
    float o00 = s_cb2[0], o01 = s_cb2[1];
    float o10 = s_cb2[0], o11 = s_cb2[1];
    #pragma unroll
    for (int m = 0; m < 16; m++) {
        float w = s_cW1[m], bbq = s_cb1[m];
        float w20 = s_cW2[2*m], w21 = s_cW2[2*m+1];
        float h0 = fmaxf(fmaf(q0, w, bbq), 0.f);
        float h1 = fmaxf(fmaf(q1, w, bbq), 0.f);
        o00 = fmaf(h0, w20, o00); o01 = fmaf(h0, w21, o01);
        o10 = fmaf(h1, w20, o10); o11 = fmaf(h1, w21, o11);
    }
    ((float2*)out)[b0] = make_float2(o00, o01);
    ((float2*)out)[b1] = make_float2(o10, o11);
}

extern "C" void kernel_launch(void* const* d_in, const int* in_sizes, int n_in,
                              void* d_out, int out_size) {
    const float* text = (const float*)d_in[0];
    const float* image = (const float*)d_in[1];
    const float* tW1 = (const float*)d_in[2];
    const float* tb1 = (const float*)d_in[3];
    const float* tW2 = (const float*)d_in[4];
    const float* tb2 = (const float*)d_in[5];
    const float* iW1 = (const float*)d_in[6];
    const float* ib1 = (const float*)d_in[7];
    const float* iW2 = (const float*)d_in[8];
    const float* ib2 = (const float*)d_in[9];
    const float* qweights = (const float*)d_in[10];
    const float* cW1 = (const float*)d_in[11];
    const float* cb1 = (const float*)d_in[12];
    const float* cW2 = (const float*)d_in[13];
    const float* cb2 = (const float*)d_in[14];
    float* out = (float*)d_out;

    int B = in_sizes[0] / 16;  // 524288
    qnn_setup_kernel<<<1, 256>>>(qweights);
    qnn_main_kernel<<<B / SPB, NT>>>(text, image, tW1, tb1, tW2, tb2,
                                     iW1, ib1, iW2, ib2,
                                     cW1, cb1, cW2, cb2, out);
}

// round 12
// speedup vs baseline: 1.1090x; 1.1090x over previous
#include <cuda_runtime.h>
#include <cuda_bf16.h>

#define NQ 4
#define NL 2
#define NT 128
#define S  4
#define SPB (S * NT)   // 512 samples per block

typedef unsigned long long ull;

__device__ float d_T[108];  // 27 float4 rows: T[w0*9+w1*3+w2][w3], pad=0

__device__ __forceinline__ ull pack2(float lo, float hi) {
    ull r; asm("mov.b64 %0, {%1, %2};" : "=l"(r) : "f"(lo), "f"(hi)); return r;
}
__device__ __forceinline__ ull dup2(float x) { return pack2(x, x); }
__device__ __forceinline__ void unpack2(ull v, float& lo, float& hi) {
    asm("mov.b64 {%0, %1}, %2;" : "=f"(lo), "=f"(hi) : "l"(v));
}
__device__ __forceinline__ ull ffma2(ull a, ull b, ull c) {
    ull d; asm("fma.rn.f32x2 %0, %1, %2, %3;" : "=l"(d) : "l"(a), "l"(b), "l"(c)); return d;
}

__device__ __forceinline__ float2 cmul(float2 a, float2 b) {
    return make_float2(a.x * b.x - a.y * b.y, a.x * b.y + a.y * b.x);
}
__device__ __forceinline__ float2 cadd(float2 a, float2 b) {
    return make_float2(a.x + b.x, a.y + b.y);
}

// Build fixed circuit unitary U from qweights, A = Re(U^dag Z0 U), then the
// 81-coeff trig tensor T. For each w, exactly 16 (j,k) terms are nonzero:
//   w_i=0: (0,0)+0.5, (1,1)+0.5 ; w_i=1: (0,0)+0.5, (1,1)-0.5 ; w_i=2: (0,1)+0.5, (1,0)+0.5
__global__ void qnn_setup_kernel(const float* __restrict__ qw) {
    __shared__ float2 U[16][16];
    __shared__ float sA[256];
    int t = threadIdx.x;  // 256 threads
    {
        int r = t >> 4, c = t & 15;
        U[r][c] = make_float2(r == c ? 1.f : 0.f, 0.f);
    }
    __syncthreads();

    for (int l = 0; l < NL; l++) {
        for (int i = 0; i < NQ; i++) {
            float phi = qw[(l * NQ + i) * 3 + 0];
            float th  = qw[(l * NQ + i) * 3 + 1];
            float om  = qw[(l * NQ + i) * 3 + 2];
            float ct = cosf(0.5f * th), st = sinf(0.5f * th);
            float ap = 0.5f * (phi + om), am = 0.5f * (phi - om);
            float cap = cosf(ap), sap = sinf(ap);
            float cam = cosf(am), sam = sinf(am);
            float2 g00 = make_float2( cap * ct, -sap * ct);
            float2 g01 = make_float2(-cam * st, -sam * st);
            float2 g10 = make_float2( cam * st, -sam * st);
            float2 g11 = make_float2( cap * ct,  sap * ct);
            int bit = 3 - i;
            if (t < 128) {
                int pair = t >> 4;
                int c = t & 15;
                int low = pair & ((1 << bit) - 1);
                int hi  = pair >> bit;
                int r0  = (hi << (bit + 1)) | low;
                int r1  = r0 | (1 << bit);
                float2 u0 = U[r0][c], u1 = U[r1][c];
                U[r0][c] = cadd(cmul(g00, u0), cmul(g01, u1));
                U[r1][c] = cadd(cmul(g10, u0), cmul(g11, u1));
            }
            __syncthreads();
        }
        {
            int r = t >> 4, c = t & 15;
            float sign = 1.f;
            if (((r >> 3) & 1) && ((r >> 2) & 1)) sign = -sign;
            if (((r >> 2) & 1) && ((r >> 1) & 1)) sign = -sign;
            if (((r >> 1) & 1) && (r & 1))        sign = -sign;
            U[r][c].x *= sign;
            U[r][c].y *= sign;
        }
        __syncthreads();
    }

    // A[j][k] = sum_r z(r) * Re(conj(U[r][j]) * U[r][k])
    {
        int j = t >> 4, k = t & 15;
        float acc = 0.f;
        #pragma unroll
        for (int r = 0; r < 16; r++) {
            float z = (r & 8) ? -1.f : 1.f;
            acc += z * (U[r][j].x * U[r][k].x + U[r][j].y * U[r][k].y);
        }
        sA[j * 16 + k] = acc;
    }
    __syncthreads();

    // T: 81 coefficients, each a 16-term sum (deterministic, no atomics).
    if (t < 81) {
        int w[4] = {t / 27, (t / 9) % 3, (t / 3) % 3, t % 3};
        float sum = 0.f;
        #pragma unroll
        for (int m = 0; m < 16; m++) {
            int j = 0, k = 0; float c = 1.f;
            #pragma unroll
            for (int i = 0; i < 4; i++) {
                int o = (m >> i) & 1;
                int ji, ki; float ci;
                if (w[i] == 2) { ji = o ? 1 : 0; ki = o ? 0 : 1; ci = 0.5f; }
                else           { ji = o; ki = o; ci = (w[i] == 1 && o == 1) ? -0.5f : 0.5f; }
                j |= ji << (3 - i); k |= ki << (3 - i);
                c *= ci;
            }
            sum += c * sA[j * 16 + k];
        }
        d_T[(t / 3) * 4 + (t % 3)] = sum;   // row = w0*9+w1*3+w2, comp = w3
    }
    if (t < 27) d_T[t * 4 + 3] = 0.f;  // pad
}

__global__ __launch_bounds__(NT, 2) void qnn_main_kernel(
    const float* __restrict__ text, const float* __restrict__ image,
    const float* __restrict__ tW1, const float* __restrict__ tb1,
    const float* __restrict__ tW2, const float* __restrict__ tb2,
    const float* __restrict__ iW1, const float* __restrict__ ib1,
    const float* __restrict__ iW2, const float* __restrict__ ib2,
    const float* __restrict__ cW1, const float* __restrict__ cb1,
    const float* __restrict__ cW2, const float* __restrict__ cb2,
    float* __restrict__ out)
{
    __shared__ __align__(16) float s_tW1[16 * 32];
    __shared__ __align__(16) float s_tb1[32];
    __shared__ __align__(16) float s_tW2[32 * 4];
    __shared__ __align__(16) float s_iW1[48 * 64];
    __shared__ __align__(16) float s_ib1[64];
    __shared__ __align__(16) float s_iW2[64 * 4];
    __shared__ __align__(16) float s_T[108];
    __shared__ float s_tb2[4], s_ib2[4];
    __shared__ float s_cW1[16], s_cb1[16], s_cW2[32], s_cb2[2];

    int tid = threadIdx.x;
    for (int i = tid; i < 512; i += NT) s_tW1[i] = tW1[i];
    for (int i = tid; i < 3072; i += NT) s_iW1[i] = iW1[i];
    for (int i = tid; i < 256; i += NT) s_iW2[i] = iW2[i];
    if (tid < 128) s_tW2[tid] = tW2[tid];
    if (tid < 108) s_T[tid] = d_T[tid];
    if (tid < 64) s_ib1[tid] = ib1[tid];
    if (tid < 32) { s_tb1[tid] = tb1[tid]; s_cW2[tid] = cW2[tid]; }
    if (tid < 16) { s_cW1[tid] = cW1[tid]; s_cb1[tid] = cb1[tid]; }
    if (tid < 4) { s_tb2[tid] = tb2[tid]; s_ib2[tid] = ib2[tid]; }
    if (tid < 2) s_cb2[tid] = cb2[tid];
    __syncthreads();

    int base = blockIdx.x * SPB + tid;   // sample s at base + s*NT

    float fb0 = s_tb2[0] + s_ib2[0];
    float fb1 = s_tb2[1] + s_ib2[1];
    float fb2 = s_tb2[2] + s_ib2[2];
    float fb3 = s_tb2[3] + s_ib2[3];
    float fa[S][4];
    #pragma unroll
    for (int s = 0; s < S; s++) { fa[s][0] = fb0; fa[s][1] = fb1; fa[s][2] = fb2; fa[s][3] = fb3; }

    // ---- text MLP: 16 -> 32 (relu) -> 4; 4 samples, 2 j-passes of 16 ----
    #pragma unroll
    for (int jt = 0; jt < 2; jt++) {
        ull h[S][8];
        {
            const ulonglong2* bb = (const ulonglong2*)&s_tb1[jt * 16];
            #pragma unroll
            for (int p = 0; p < 4; p++) {
                ulonglong2 v = bb[p];
                #pragma unroll
                for (int s = 0; s < S; s++) { h[s][2*p] = v.x; h[s][2*p+1] = v.y; }
            }
        }
        #pragma unroll
        for (int kb = 0; kb < 4; kb++) {
            float4 v[S];
            #pragma unroll
            for (int s = 0; s < S; s++)
                v[s] = ((const float4*)(text + (size_t)(base + s * NT) * 16))[kb];
            #pragma unroll
            for (int kk = 0; kk < 4; kk++) {
                int k = 4 * kb + kk;
                ull xd[S];
                #pragma unroll
                for (int s = 0; s < S; s++) {
                    float xv = (kk == 0) ? v[s].x : (kk == 1) ? v[s].y : (kk == 2) ? v[s].z : v[s].w;
                    xd[s] = dup2(xv);
                }
                const ulonglong2* wrow = (const ulonglong2*)&s_tW1[k * 32 + jt * 16];
                #pragma unroll
                for (int p = 0; p < 4; p++) {
                    ulonglong2 w = wrow[p];
                    #pragma unroll
                    for (int s = 0; s < S; s++) {
                        h[s][2*p]   = ffma2(xd[s], w.x, h[s][2*p]);
                        h[s][2*p+1] = ffma2(xd[s], w.y, h[s][2*p+1]);
                    }
                }
            }
        }
        #pragma unroll
        for (int m = 0; m < 8; m++) {
            int r = jt * 16 + 2 * m;
            float4 w0 = *(const float4*)&s_tW2[r * 4];
            float4 w1 = *(const float4*)&s_tW2[(r + 1) * 4];
            #pragma unroll
            for (int s = 0; s < S; s++) {
                float ha, hb;
                unpack2(h[s][m], ha, hb);
                ha = fmaxf(ha, 0.f); hb = fmaxf(hb, 0.f);
                fa[s][0] = fmaf(ha, w0.x, fa[s][0]); fa[s][1] = fmaf(ha, w0.y, fa[s][1]);
                fa[s][2] = fmaf(ha, w0.z, fa[s][2]); fa[s][3] = fmaf(ha, w0.w, fa[s][3]);
                fa[s][0] = fmaf(hb, w1.x, fa[s][0]); fa[s][1] = fmaf(hb, w1.y, fa[s][1]);
                fa[s][2] = fmaf(hb, w1.z, fa[s][2]); fa[s][3] = fmaf(hb, w1.w, fa[s][3]);
            }
        }
    }

    // ---- image MLP: 48 -> 64 (relu) -> 4; 4 samples, 4 j-passes of 16 ----
    #pragma unroll
    for (int jt = 0; jt < 4; jt++) {
        ull h[S][8];
        {
            const ulonglong2* bb = (const ulonglong2*)&s_ib1[jt * 16];
            #pragma unroll
            for (int p = 0; p < 4; p++) {
                ulonglong2 v = bb[p];
                #pragma unroll
                for (int s = 0; s < S; s++) { h[s][2*p] = v.x; h[s][2*p+1] = v.y; }
            }
        }
        #pragma unroll 4
        for (int kb = 0; kb < 12; kb++) {
            float4 v[S];
            #pragma unroll
            for (int s = 0; s < S; s++)
                v[s] = ((const float4*)(image + (size_t)(base + s * NT) * 48))[kb];
            #pragma unroll
            for (int kk = 0; kk < 4; kk++) {
                int k = 4 * kb + kk;
                ull xd[S];
                #pragma unroll
                for (int s = 0; s < S; s++) {
                    float xv = (kk == 0) ? v[s].x : (kk == 1) ? v[s].y : (kk == 2) ? v[s].z : v[s].w;
                    xd[s] = dup2(xv);
                }
                const ulonglong2* wrow = (const ulonglong2*)&s_iW1[k * 64 + jt * 16];
                #pragma unroll
                for (int p = 0; p < 4; p++) {
                    ulonglong2 w = wrow[p];
                    #pragma unroll
                    for (int s = 0; s < S; s++) {
                        h[s][2*p]   = ffma2(xd[s], w.x, h[s][2*p]);
                        h[s][2*p+1] = ffma2(xd[s], w.y, h[s][2*p+1]);
                    }
                }
            }
        }
        #pragma unroll
        for (int m = 0; m < 8; m++) {
            int r = jt * 16 + 2 * m;
            float4 w0 = *(const float4*)&s_iW2[r * 4];
            float4 w1 = *(const float4*)&s_iW2[(r + 1) * 4];
            #pragma unroll
            for (int s = 0; s < S; s++) {
                float ha, hb;
                unpack2(h[s][m], ha, hb);
                ha = fmaxf(ha, 0.f); hb = fmaxf(hb, 0.f);
                fa[s][0] = fmaf(ha, w0.x, fa[s][0]); fa[s][1] = fmaf(ha, w0.y, fa[s][1]);
                fa[s][2] = fmaf(ha, w0.z, fa[s][2]); fa[s][3] = fmaf(ha, w0.w, fa[s][3]);
                fa[s][0] = fmaf(hb, w1.x, fa[s][0]); fa[s][1] = fmaf(hb, w1.y, fa[s][1]);
                fa[s][2] = fmaf(hb, w1.z, fa[s][2]); fa[s][3] = fmaf(hb, w1.w, fa[s][3]);
            }
        }
    }

    // ---- quantum: f_i = 0.5*acc_i (FULL angle); q = T contraction ----
    float ca[S][4], sa[S][4];
    #pragma unroll
    for (int s = 0; s < S; s++)
        #pragma unroll
        for (int i = 0; i < 4; i++)
            __sincosf(0.5f * fa[s][i], &sa[s][i], &ca[s][i]);

    float Bv[S][9];
    #pragma unroll
    for (int s = 0; s < S; s++) {
        Bv[s][0] = 1.f;
        Bv[s][1] = ca[s][1];             Bv[s][2] = sa[s][1];
        Bv[s][3] = ca[s][0];             Bv[s][4] = ca[s][0] * ca[s][1];
        Bv[s][5] = ca[s][0] * sa[s][1];  Bv[s][6] = sa[s][0];
        Bv[s][7] = sa[s][0] * ca[s][1];  Bv[s][8] = sa[s][0] * sa[s][1];
    }

    float q[S] = {0.f, 0.f, 0.f, 0.f};
    #pragma unroll
    for (int n = 0; n < 9; n++) {
        float s2[S] = {0.f, 0.f, 0.f, 0.f};
        #pragma unroll
        for (int w2 = 0; w2 < 3; w2++) {
            float4 tr = *(const float4*)&s_T[(n * 3 + w2) * 4];   // shared by 4 samples
            #pragma unroll
            for (int s = 0; s < S; s++) {
                float d = fmaf(tr.z, sa[s][3], fmaf(tr.y, ca[s][3], tr.x));
                float u2 = (w2 == 0) ? 1.f : (w2 == 1) ? ca[s][2] : sa[s][2];
                s2[s] = fmaf(u2, d, s2[s]);
            }
        }
        #pragma unroll
        for (int s = 0; s < S; s++) q[s] = fmaf(Bv[s][n], s2[s], q[s]);
    }

    // ---- classifier: q -> 16 (relu) -> 2; shared weight loads ----
    float o0[S], o1[S];
    #pragma unroll
    for (int s = 0; s < S; s++) { o0[s] = s_cb2[0]; o1[s] = s_cb2[1]; }
    #pragma unroll
    for (int m = 0; m < 16; m++) {
        float w = s_cW1[m], bq = s_cb1[m];
        float w20 = s_cW2[2*m], w21 = s_cW2[2*m+1];
        #pragma unroll
        for (int s = 0; s < S; s++) {
            float hh = fmaxf(fmaf(q[s], w, bq), 0.f);
            o0[s] = fmaf(hh, w20, o0[s]);
            o1[s] = fmaf(hh, w21, o1[s]);
        }
    }
    #pragma unroll
    for (int s = 0; s < S; s++)
        ((float2*)out)[base + s * NT] = make_float2(o0[s], o1[s]);
}

extern "C" void kernel_launch(void* const* d_in, const int* in_sizes, int n_in,
                              void* d_out, int out_size) {
    const float* text = (const float*)d_in[0];
    const float* image = (const float*)d_in[1];
    const float* tW1 = (const float*)d_in[2];
    const float* tb1 = (const float*)d_in[3];
    const float* tW2 = (const float*)d_in[4];
    const float* tb2 = (const float*)d_in[5];
    const float* iW1 = (const float*)d_in[6];
    const float* ib1 = (const float*)d_in[7];
    const float* iW2 = (const float*)d_in[8];
    const float* ib2 = (const float*)d_in[9];
    const float* qweights = (const float*)d_in[10];
    const float* cW1 = (const float*)d_in[11];
    const float* cb1 = (const float*)d_in[12];
    const float* cW2 = (const float*)d_in[13];
    const float* cb2 = (const float*)d_in[14];
    float* out = (float*)d_out;

    int B = in_sizes[0] / 16;  // 524288
    qnn_setup_kernel<<<1, 256>>>(qweights);
    qnn_main_kernel<<<B / SPB, NT>>>(text, image, tW1, tb1, tW2, tb2,
                                     iW1, ib1, iW2, ib2,
                                     cW1, cb1, cW2, cb2, out);
}

// round 15
// speedup vs baseline: 1.6881x; 1.5221x over previous
#include <cuda_runtime.h>
#include <cuda_bf16.h>
#include <cstdint>

#define NQ 4
#define NL 2
#define NT 128
#define TILE_M 128

// ---- device globals prepared by setup kernel ----
__device__ float d_T[108];                      // trig tensor, 27 float4 rows
__device__ uint2 d_Bfrag[2 * 12 * 4 * 32];      // [pass hi/lo][ntile][kchunk][lane] mma B-fragments
__device__ float d_bias[96];                    // tb1 | ib1
__device__ float d_W2[96 * 4];                  // tW2 | iW2 rows
__device__ float d_fb[4];                       // tb2 + ib2

__device__ __forceinline__ uint32_t smem_u32(const void* p) {
    uint32_t a;
    asm("{ .reg .u64 t; cvta.to.shared.u64 t, %1; cvt.u32.u64 %0, t; }" : "=r"(a) : "l"(p));
    return a;
}
__device__ __forceinline__ uint32_t sw128(uint32_t b) { return b ^ ((b >> 3) & 0x70); }

__device__ __forceinline__ float2 cmul(float2 a, float2 b) {
    return make_float2(a.x * b.x - a.y * b.y, a.x * b.y + a.y * b.x);
}
__device__ __forceinline__ float2 cadd(float2 a, float2 b) {
    return make_float2(a.x + b.x, a.y + b.y);
}

#define MMA_BF16(C, A, B) \
    asm volatile("mma.sync.aligned.m16n8k16.row.col.f32.bf16.bf16.f32 " \
        "{%0,%1,%2,%3}, {%4,%5,%6,%7}, {%8,%9}, {%0,%1,%2,%3};" \
        : "+f"((C)[0]), "+f"((C)[1]), "+f"((C)[2]), "+f"((C)[3]) \
        : "r"((A)[0]), "r"((A)[1]), "r"((A)[2]), "r"((A)[3]), "r"((B).x), "r"((B).y))

#define LDM_X4(R, addr) \
    asm volatile("ldmatrix.sync.aligned.m8n8.x4.shared.b16 {%0,%1,%2,%3}, [%4];" \
        : "=r"((R)[0]), "=r"((R)[1]), "=r"((R)[2]), "=r"((R)[3]) : "r"(addr))

// ---- setup: trig tensor T + B mma-fragments (hi/lo) + fused bias/W2 ----
__global__ void qnn_setup_kernel(
    const float* __restrict__ qw,
    const float* __restrict__ tW1, const float* __restrict__ tb1,
    const float* __restrict__ tW2, const float* __restrict__ tb2,
    const float* __restrict__ iW1, const float* __restrict__ ib1,
    const float* __restrict__ iW2, const float* __restrict__ ib2)
{
    __shared__ float2 U[16][16];
    __shared__ float sA[256];
    int t = threadIdx.x;  // 256 threads
    {
        int r = t >> 4, c = t & 15;
        U[r][c] = make_float2(r == c ? 1.f : 0.f, 0.f);
    }
    __syncthreads();

    for (int l = 0; l < NL; l++) {
        for (int i = 0; i < NQ; i++) {
            float phi = qw[(l * NQ + i) * 3 + 0];
            float th  = qw[(l * NQ + i) * 3 + 1];
            float om  = qw[(l * NQ + i) * 3 + 2];
            float ct = cosf(0.5f * th), st = sinf(0.5f * th);
            float ap = 0.5f * (phi + om), am = 0.5f * (phi - om);
            float cap = cosf(ap), sap = sinf(ap);
            float cam = cosf(am), sam = sinf(am);
            float2 g00 = make_float2( cap * ct, -sap * ct);
            float2 g01 = make_float2(-cam * st, -sam * st);
            float2 g10 = make_float2( cam * st, -sam * st);
            float2 g11 = make_float2( cap * ct,  sap * ct);
            int bit = 3 - i;
            if (t < 128) {
                int pair = t >> 4, c = t & 15;
                int low = pair & ((1 << bit) - 1);
                int hi  = pair >> bit;
                int r0  = (hi << (bit + 1)) | low;
                int r1  = r0 | (1 << bit);
                float2 u0 = U[r0][c], u1 = U[r1][c];
                U[r0][c] = cadd(cmul(g00, u0), cmul(g01, u1));
                U[r1][c] = cadd(cmul(g10, u0), cmul(g11, u1));
            }
            __syncthreads();
        }
        {
            int r = t >> 4, c = t & 15;
            float sign = 1.f;
            if (((r >> 3) & 1) && ((r >> 2) & 1)) sign = -sign;
            if (((r >> 2) & 1) && ((r >> 1) & 1)) sign = -sign;
            if (((r >> 1) & 1) && (r & 1))        sign = -sign;
            U[r][c].x *= sign; U[r][c].y *= sign;
        }
        __syncthreads();
    }
    {
        int j = t >> 4, k = t & 15;
        float acc = 0.f;
        #pragma unroll
        for (int r = 0; r < 16; r++) {
            float z = (r & 8) ? -1.f : 1.f;
            acc += z * (U[r][j].x * U[r][k].x + U[r][j].y * U[r][k].y);
        }
        sA[j * 16 + k] = acc;
    }
    __syncthreads();

    if (t < 81) {
        int w[4] = {t / 27, (t / 9) % 3, (t / 3) % 3, t % 3};
        float sum = 0.f;
        #pragma unroll
        for (int m = 0; m < 16; m++) {
            int j = 0, k = 0; float c = 1.f;
            #pragma unroll
            for (int i = 0; i < 4; i++) {
                int o = (m >> i) & 1;
                int ji, ki; float ci;
                if (w[i] == 2) { ji = o ? 1 : 0; ki = o ? 0 : 1; ci = 0.5f; }
                else           { ji = o; ki = o; ci = (w[i] == 1 && o == 1) ? -0.5f : 0.5f; }
                j |= ji << (3 - i); k |= ki << (3 - i);
                c *= ci;
            }
            sum += c * sA[j * 16 + k];
        }
        d_T[(t / 3) * 4 + (t % 3)] = sum;
    }
    if (t < 27) d_T[t * 4 + 3] = 0.f;

    // B[k=0..63][n=0..95] block-diagonal layer-1 weights -> mma B fragments.
    // frag b0 = bf16x2 {B[k0][n], B[k0+1][n]}, b1 = {B[k0+8][n], B[k0+9][n]},
    // k0 = c*16 + (lane%4)*2, n = ntile*8 + lane/4.
    for (int idx = t; idx < 2 * 12 * 4 * 32; idx += 256) {
        int p = idx / 1536;
        int r = idx % 1536;
        int nt = r / 128;
        int r2 = r % 128;
        int c = r2 / 32;
        int lane = r2 % 32;
        int n = nt * 8 + (lane >> 2);
        int k0 = c * 16 + (lane & 3) * 2;
        float wv[4];
        #pragma unroll
        for (int e = 0; e < 4; e++) {
            int k = k0 + (e & 1) + (e >> 1) * 8;
            float w = 0.f;
            if (n < 32) { if (k < 16)  w = tW1[k * 32 + n]; }
            else        { if (k >= 16) w = iW1[(k - 16) * 64 + (n - 32)]; }
            __nv_bfloat16 h = __float2bfloat16(w);
            wv[e] = p == 0 ? __bfloat162float(h) : (w - __bfloat162float(h));
        }
        __nv_bfloat162 b0; b0.x = __float2bfloat16(wv[0]); b0.y = __float2bfloat16(wv[1]);
        __nv_bfloat162 b1; b1.x = __float2bfloat16(wv[2]); b1.y = __float2bfloat16(wv[3]);
        uint2 out;
        out.x = *(uint32_t*)&b0;
        out.y = *(uint32_t*)&b1;
        d_Bfrag[idx] = out;
    }
    if (t < 96) d_bias[t] = (t < 32) ? tb1[t] : ib1[t - 32];
    for (int idx = t; idx < 96 * 4; idx += 256) {
        int n = idx >> 2, j = idx & 3;
        d_W2[idx] = (n < 32) ? tW2[n * 4 + j] : iW2[(n - 32) * 4 + j];
    }
    if (t < 4) d_fb[t] = tb2[t] + ib2[t];
}

// ---- main: warp-level HMMA GEMM for both MLPs + fragment epilogue ----
__global__ __launch_bounds__(NT, 3) void qnn_mma_kernel(
    const float* __restrict__ text, const float* __restrict__ image,
    const float* __restrict__ cW1, const float* __restrict__ cb1,
    const float* __restrict__ cW2, const float* __restrict__ cb2,
    float* __restrict__ out)
{
    __shared__ __align__(16) unsigned char sAhi[128 * 128];  // A hi: 128 rows x 64 bf16, SW128
    __shared__ __align__(16) unsigned char sAlo[128 * 128];  // A lo residual
    __shared__ __align__(16) float s_W2[96 * 4];
    __shared__ __align__(16) float s_T[108];
    __shared__ __align__(16) float s_bias[96];
    __shared__ float s_cls[70];  // cW1[0:16) cb1[16:32) cW2[32:64) cb2[64:66) fb[66:70)

    int tid = threadIdx.x;
    int lane = tid & 31, wid = tid >> 5;
    int g = lane >> 2, t4 = lane & 3;
    int gb = blockIdx.x * TILE_M + tid;

    // small tables
    {
        if (tid < 16) s_cls[tid] = cW1[tid];
        else if (tid < 32) s_cls[tid] = cb1[tid - 16];
        else if (tid < 64) s_cls[tid] = cW2[tid - 32];
        else if (tid < 66) s_cls[tid] = cb2[tid - 64];
        else if (tid < 70) s_cls[tid] = d_fb[tid - 66];
        if (tid < 96) s_bias[tid] = d_bias[tid];
        if (tid < 108) s_T[tid] = d_T[tid];
        s_W2[tid] = d_W2[tid];
        s_W2[tid + 128] = d_W2[tid + 128];
        s_W2[tid + 256] = d_W2[tid + 256];
    }

    // stage A: this thread's sample -> row tid, x = [text(16) | image(48)], hi/lo bf16, SW128
    {
        float xv[64];
        const float4* tp = (const float4*)(text + (size_t)gb * 16);
        #pragma unroll
        for (int i = 0; i < 4; i++) {
            float4 v = tp[i];
            xv[4*i+0] = v.x; xv[4*i+1] = v.y; xv[4*i+2] = v.z; xv[4*i+3] = v.w;
        }
        const float4* ip = (const float4*)(image + (size_t)gb * 48);
        #pragma unroll
        for (int i = 0; i < 12; i++) {
            float4 v = ip[i];
            xv[16+4*i+0] = v.x; xv[16+4*i+1] = v.y; xv[16+4*i+2] = v.z; xv[16+4*i+3] = v.w;
        }
        #pragma unroll
        for (int i = 0; i < 8; i++) {   // 8 bf16 = 16B per store
            uint32_t hw[4], lw[4];
            #pragma unroll
            for (int p = 0; p < 4; p++) {
                float x0 = xv[8*i + 2*p], x1 = xv[8*i + 2*p + 1];
                __nv_bfloat162 hv, lv;
                hv.x = __float2bfloat16(x0); hv.y = __float2bfloat16(x1);
                lv.x = __float2bfloat16(x0 - __bfloat162float(hv.x));
                lv.y = __float2bfloat16(x1 - __bfloat162float(hv.y));
                hw[p] = *(uint32_t*)&hv;
                lw[p] = *(uint32_t*)&lv;
            }
            uint32_t sw = sw128((uint32_t)(tid * 128 + i * 16));
            *(uint4*)(sAhi + sw) = make_uint4(hw[0], hw[1], hw[2], hw[3]);
            *(uint4*)(sAlo + sw) = make_uint4(lw[0], lw[1], lw[2], lw[3]);
        }
    }
    __syncthreads();

    uint32_t sbAhi = smem_u32(sAhi), sbAlo = smem_u32(sAlo);
    // ldmatrix per-lane source row/col within a 16x16 tile
    int lrow = (lane & 7) + ((lane >> 3) & 1) * 8;
    int lcol = ((lane >> 4) & 1) * 16;
    int warpRow = wid * 32;

    float fp[2][2][4];
    #pragma unroll
    for (int m = 0; m < 2; m++)
        #pragma unroll
        for (int h = 0; h < 2; h++)
            #pragma unroll
            for (int j = 0; j < 4; j++) fp[m][h][j] = 0.f;

    #pragma unroll
    for (int nc = 0; nc < 3; nc++) {
        float C[2][4][4];
        #pragma unroll
        for (int m = 0; m < 2; m++)
            #pragma unroll
            for (int tt = 0; tt < 4; tt++)
                #pragma unroll
                for (int e = 0; e < 4; e++) C[m][tt][e] = 0.f;

        #pragma unroll
        for (int c = 0; c < 4; c++) {
            uint32_t ah[2][4], al[2][4];
            #pragma unroll
            for (int m = 0; m < 2; m++) {
                uint32_t sw = sw128((uint32_t)((warpRow + m * 16 + lrow) * 128 + c * 32 + lcol));
                LDM_X4(ah[m], sbAhi + sw);
                LDM_X4(al[m], sbAlo + sw);
            }
            #pragma unroll
            for (int tt = 0; tt < 4; tt++) {
                int fi = ((nc * 4 + tt) * 4 + c) * 32 + lane;
                uint2 bh = d_Bfrag[fi];
                uint2 bl = d_Bfrag[1536 + fi];
                #pragma unroll
                for (int m = 0; m < 2; m++) {
                    MMA_BF16(C[m][tt], ah[m], bh);
                    MMA_BF16(C[m][tt], al[m], bh);
                    MMA_BF16(C[m][tt], ah[m], bl);
                }
            }
        }
        // fragment epilogue: bias + relu + layer-2 partials
        #pragma unroll
        for (int tt = 0; tt < 4; tt++) {
            int n0 = nc * 32 + tt * 8 + t4 * 2;
            float2 bs = *(const float2*)&s_bias[n0];
            float4 w0 = *(const float4*)&s_W2[n0 * 4];
            float4 w1 = *(const float4*)&s_W2[(n0 + 1) * 4];
            #pragma unroll
            for (int m = 0; m < 2; m++) {
                float h0 = fmaxf(C[m][tt][0] + bs.x, 0.f);   // row g,   col n0
                float h1 = fmaxf(C[m][tt][1] + bs.y, 0.f);   // row g,   col n0+1
                float h2 = fmaxf(C[m][tt][2] + bs.x, 0.f);   // row g+8, col n0
                float h3 = fmaxf(C[m][tt][3] + bs.y, 0.f);   // row g+8, col n0+1
                fp[m][0][0] = fmaf(h0, w0.x, fmaf(h1, w1.x, fp[m][0][0]));
                fp[m][0][1] = fmaf(h0, w0.y, fmaf(h1, w1.y, fp[m][0][1]));
                fp[m][0][2] = fmaf(h0, w0.z, fmaf(h1, w1.z, fp[m][0][2]));
                fp[m][0][3] = fmaf(h0, w0.w, fmaf(h1, w1.w, fp[m][0][3]));
                fp[m][1][0] = fmaf(h2, w0.x, fmaf(h3, w1.x, fp[m][1][0]));
                fp[m][1][1] = fmaf(h2, w0.y, fmaf(h3, w1.y, fp[m][1][1]));
                fp[m][1][2] = fmaf(h2, w0.z, fmaf(h3, w1.z, fp[m][1][2]));
                fp[m][1][3] = fmaf(h2, w0.w, fmaf(h3, w1.w, fp[m][1][3]));
            }
        }
    }

    // quad reduction (lanes 4g..4g+3 hold the same rows, different col ranges)
    #pragma unroll
    for (int m = 0; m < 2; m++)
        #pragma unroll
        for (int h = 0; h < 2; h++)
            #pragma unroll
            for (int j = 0; j < 4; j++) {
                float v = fp[m][h][j];
                v += __shfl_xor_sync(0xffffffffu, v, 1);
                v += __shfl_xor_sync(0xffffffffu, v, 2);
                fp[m][h][j] = v;
            }

    // each quad lane takes one of the 4 rows
    int sel = t4;
    float fa[4];
    #pragma unroll
    for (int j = 0; j < 4; j++) {
        float v0 = (sel & 1) ? fp[0][1][j] : fp[0][0][j];
        float v1 = (sel & 1) ? fp[1][1][j] : fp[1][0][j];
        fa[j] = ((sel >> 1) ? v1 : v0) + s_cls[66 + j];
    }
    int rowLocal = warpRow + ((sel >> 1) << 4) + ((sel & 1) << 3) + g;

    // quantum: full angle f = 0.5*feats_sum; q = T contraction
    float ca[4], sa[4];
    #pragma unroll
    for (int i = 0; i < 4; i++) __sincosf(0.5f * fa[i], &sa[i], &ca[i]);
    float Bv[9] = {1.f, ca[1], sa[1], ca[0], ca[0]*ca[1], ca[0]*sa[1], sa[0], sa[0]*ca[1], sa[0]*sa[1]};
    float q = 0.f;
    #pragma unroll
    for (int n = 0; n < 9; n++) {
        float s2 = 0.f;
        #pragma unroll
        for (int w2 = 0; w2 < 3; w2++) {
            float4 tr = *(const float4*)&s_T[(n * 3 + w2) * 4];
            float dd = fmaf(tr.z, sa[3], fmaf(tr.y, ca[3], tr.x));
            float u2 = (w2 == 0) ? 1.f : (w2 == 1) ? ca[2] : sa[2];
            s2 = fmaf(u2, dd, s2);
        }
        q = fmaf(Bv[n], s2, q);
    }

    // classifier
    float o0 = s_cls[64], o1 = s_cls[65];
    #pragma unroll
    for (int m = 0; m < 16; m++) {
        float h = fmaxf(fmaf(q, s_cls[m], s_cls[16 + m]), 0.f);
        o0 = fmaf(h, s_cls[32 + 2*m], o0);
        o1 = fmaf(h, s_cls[32 + 2*m + 1], o1);
    }
    ((float2*)out)[blockIdx.x * TILE_M + rowLocal] = make_float2(o0, o1);
}

extern "C" void kernel_launch(void* const* d_in, const int* in_sizes, int n_in,
                              void* d_out, int out_size) {
    const float* text = (const float*)d_in[0];
    const float* image = (const float*)d_in[1];
    const float* tW1 = (const float*)d_in[2];
    const float* tb1 = (const float*)d_in[3];
    const float* tW2 = (const float*)d_in[4];
    const float* tb2 = (const float*)d_in[5];
    const float* iW1 = (const float*)d_in[6];
    const float* ib1 = (const float*)d_in[7];
    const float* iW2 = (const float*)d_in[8];
    const float* ib2 = (const float*)d_in[9];
    const float* qweights = (const float*)d_in[10];
    const float* cW1 = (const float*)d_in[11];
    const float* cb1 = (const float*)d_in[12];
    const float* cW2 = (const float*)d_in[13];
    const float* cb2 = (const float*)d_in[14];
    float* out = (float*)d_out;

    int B = in_sizes[0] / 16;  // 524288
    qnn_setup_kernel<<<1, 256>>>(qweights, tW1, tb1, tW2, tb2, iW1, ib1, iW2, ib2);
    qnn_mma_kernel<<<B / TILE_M, NT>>>(text, image, cW1, cb1, cW2, cb2, out);
}

// round 16
// speedup vs baseline: 1.7588x; 1.0419x over previous
#include <cuda_runtime.h>
#include <cuda_bf16.h>
#include <cstdint>

#define NQ 4
#define NL 2
#define NT 128
#define TILE_M 128

// ---- device globals prepared by setup kernel ----
__device__ float d_T[108];                      // trig tensor, 27 float4 rows
__device__ uint2 d_Bfrag[2 * 12 * 4 * 32];      // [pass hi/lo][ntile][kchunk][lane] mma B-fragments
__device__ float d_bias[96];                    // tb1 | ib1
__device__ float d_W2[96 * 4];                  // tW2 | iW2 rows
__device__ float d_fb[4];                       // tb2 + ib2

__device__ __forceinline__ uint32_t smem_u32(const void* p) {
    uint32_t a;
    asm("{ .reg .u64 t; cvta.to.shared.u64 t, %1; cvt.u32.u64 %0, t; }" : "=r"(a) : "l"(p));
    return a;
}
__device__ __forceinline__ uint32_t sw128(uint32_t b) { return b ^ ((b >> 3) & 0x70); }

__device__ __forceinline__ float2 cmul(float2 a, float2 b) {
    return make_float2(a.x * b.x - a.y * b.y, a.x * b.y + a.y * b.x);
}
__device__ __forceinline__ float2 cadd(float2 a, float2 b) {
    return make_float2(a.x + b.x, a.y + b.y);
}

#define MMA_BF16(C, A, B) \
    asm volatile("mma.sync.aligned.m16n8k16.row.col.f32.bf16.bf16.f32 " \
        "{%0,%1,%2,%3}, {%4,%5,%6,%7}, {%8,%9}, {%0,%1,%2,%3};" \
        : "+f"((C)[0]), "+f"((C)[1]), "+f"((C)[2]), "+f"((C)[3]) \
        : "r"((A)[0]), "r"((A)[1]), "r"((A)[2]), "r"((A)[3]), "r"((B).x), "r"((B).y))

#define LDM_X4(R, addr) \
    asm volatile("ldmatrix.sync.aligned.m8n8.x4.shared.b16 {%0,%1,%2,%3}, [%4];" \
        : "=r"((R)[0]), "=r"((R)[1]), "=r"((R)[2]), "=r"((R)[3]) : "r"(addr))

// ---- setup (2 blocks): block 0 = U/T, block 1 = B-fragments + bias/W2 ----
__global__ void qnn_setup_kernel(
    const float* __restrict__ qw,
    const float* __restrict__ tW1, const float* __restrict__ tb1,
    const float* __restrict__ tW2, const float* __restrict__ tb2,
    const float* __restrict__ iW1, const float* __restrict__ ib1,
    const float* __restrict__ iW2, const float* __restrict__ ib2)
{
    int t = threadIdx.x;  // 256 threads

    if (blockIdx.x == 0) {
        // ---- circuit unitary U and trig tensor T ----
        __shared__ float2 U[16][16];
        __shared__ float sA[256];
        __shared__ float s_qw[24];
        if (t < 24) s_qw[t] = qw[t];
        {
            int r = t >> 4, c = t & 15;
            U[r][c] = make_float2(r == c ? 1.f : 0.f, 0.f);
        }
        __syncthreads();

        for (int l = 0; l < NL; l++) {
            for (int i = 0; i < NQ; i++) {
                float phi = s_qw[(l * NQ + i) * 3 + 0];
                float th  = s_qw[(l * NQ + i) * 3 + 1];
                float om  = s_qw[(l * NQ + i) * 3 + 2];
                float ct, st, cap, sap, cam, sam;
                __sincosf(0.5f * th, &st, &ct);
                __sincosf(0.5f * (phi + om), &sap, &cap);
                __sincosf(0.5f * (phi - om), &sam, &cam);
                float2 g00 = make_float2( cap * ct, -sap * ct);
                float2 g01 = make_float2(-cam * st, -sam * st);
                float2 g10 = make_float2( cam * st, -sam * st);
                float2 g11 = make_float2( cap * ct,  sap * ct);
                int bit = 3 - i;
                if (t < 128) {
                    int pair = t >> 4, c = t & 15;
                    int low = pair & ((1 << bit) - 1);
                    int hi  = pair >> bit;
                    int r0  = (hi << (bit + 1)) | low;
                    int r1  = r0 | (1 << bit);
                    float2 u0 = U[r0][c], u1 = U[r1][c];
                    U[r0][c] = cadd(cmul(g00, u0), cmul(g01, u1));
                    U[r1][c] = cadd(cmul(g10, u0), cmul(g11, u1));
                }
                __syncthreads();
            }
            {
                int r = t >> 4, c = t & 15;
                float sign = 1.f;
                if (((r >> 3) & 1) && ((r >> 2) & 1)) sign = -sign;
                if (((r >> 2) & 1) && ((r >> 1) & 1)) sign = -sign;
                if (((r >> 1) & 1) && (r & 1))        sign = -sign;
                U[r][c].x *= sign; U[r][c].y *= sign;
            }
            __syncthreads();
        }
        {
            int j = t >> 4, k = t & 15;
            float acc = 0.f;
            #pragma unroll
            for (int r = 0; r < 16; r++) {
                float z = (r & 8) ? -1.f : 1.f;
                acc += z * (U[r][j].x * U[r][k].x + U[r][j].y * U[r][k].y);
            }
            sA[j * 16 + k] = acc;
        }
        __syncthreads();

        if (t < 81) {
            int w[4] = {t / 27, (t / 9) % 3, (t / 3) % 3, t % 3};
            float sum = 0.f;
            #pragma unroll
            for (int m = 0; m < 16; m++) {
                int j = 0, k = 0; float c = 1.f;
                #pragma unroll
                for (int i = 0; i < 4; i++) {
                    int o = (m >> i) & 1;
                    int ji, ki; float ci;
                    if (w[i] == 2) { ji = o ? 1 : 0; ki = o ? 0 : 1; ci = 0.5f; }
                    else           { ji = o; ki = o; ci = (w[i] == 1 && o == 1) ? -0.5f : 0.5f; }
                    j |= ji << (3 - i); k |= ki << (3 - i);
                    c *= ci;
                }
                sum += c * sA[j * 16 + k];
            }
            d_T[(t / 3) * 4 + (t % 3)] = sum;
        }
        if (t < 27) d_T[t * 4 + 3] = 0.f;
    } else {
        // ---- B fragments (hi/lo) + bias/W2/fb, from smem-prefetched weights ----
        __shared__ float s_tW1[512];
        __shared__ float s_iW1[3072];
        for (int i = t; i < 512; i += 256) s_tW1[i] = tW1[i];
        for (int i = t; i < 3072; i += 256) s_iW1[i] = iW1[i];
        __syncthreads();

        // B[k=0..63][n=0..95] block-diagonal layer-1 weights -> mma B fragments.
        for (int idx = t; idx < 2 * 12 * 4 * 32; idx += 256) {
            int p = idx / 1536;
            int r = idx % 1536;
            int nt = r / 128;
            int r2 = r % 128;
            int c = r2 / 32;
            int lane = r2 % 32;
            int n = nt * 8 + (lane >> 2);
            int k0 = c * 16 + (lane & 3) * 2;
            float wv[4];
            #pragma unroll
            for (int e = 0; e < 4; e++) {
                int k = k0 + (e & 1) + (e >> 1) * 8;
                float w = 0.f;
                if (n < 32) { if (k < 16)  w = s_tW1[k * 32 + n]; }
                else        { if (k >= 16) w = s_iW1[(k - 16) * 64 + (n - 32)]; }
                __nv_bfloat16 h = __float2bfloat16(w);
                wv[e] = p == 0 ? __bfloat162float(h) : (w - __bfloat162float(h));
            }
            __nv_bfloat162 b0; b0.x = __float2bfloat16(wv[0]); b0.y = __float2bfloat16(wv[1]);
            __nv_bfloat162 b1; b1.x = __float2bfloat16(wv[2]); b1.y = __float2bfloat16(wv[3]);
            uint2 o;
            o.x = *(uint32_t*)&b0;
            o.y = *(uint32_t*)&b1;
            d_Bfrag[idx] = o;
        }
        if (t < 96) d_bias[t] = (t < 32) ? tb1[t] : ib1[t - 32];
        for (int idx = t; idx < 96 * 4; idx += 256) {
            int n = idx >> 2, j = idx & 3;
            d_W2[idx] = (n < 32) ? tW2[n * 4 + j] : iW2[(n - 32) * 4 + j];
        }
        if (t < 4) d_fb[t] = tb2[t] + ib2[t];
    }
}

// ---- main: warp-level HMMA GEMM, A-fragments hoisted, fragment epilogue ----
__global__ __launch_bounds__(NT, 3) void qnn_mma_kernel(
    const float* __restrict__ text, const float* __restrict__ image,
    const float* __restrict__ cW1, const float* __restrict__ cb1,
    const float* __restrict__ cW2, const float* __restrict__ cb2,
    float* __restrict__ out)
{
    __shared__ __align__(16) unsigned char sAhi[128 * 128];  // A hi: 128 rows x 64 bf16, SW128
    __shared__ __align__(16) unsigned char sAlo[128 * 128];  // A lo residual
    __shared__ __align__(16) float s_W2[96 * 4];
    __shared__ __align__(16) float s_T[108];
    __shared__ __align__(16) float s_bias[96];
    __shared__ float s_cls[70];  // cW1[0:16) cb1[16:32) cW2[32:64) cb2[64:66) fb[66:70)

    int tid = threadIdx.x;
    int lane = tid & 31, wid = tid >> 5;
    int g = lane >> 2, t4 = lane & 3;
    int gb = blockIdx.x * TILE_M + tid;

    // small tables
    {
        if (tid < 16) s_cls[tid] = cW1[tid];
        else if (tid < 32) s_cls[tid] = cb1[tid - 16];
        else if (tid < 64) s_cls[tid] = cW2[tid - 32];
        else if (tid < 66) s_cls[tid] = cb2[tid - 64];
        else if (tid < 70) s_cls[tid] = d_fb[tid - 66];
        if (tid < 96) s_bias[tid] = d_bias[tid];
        if (tid < 108) s_T[tid] = d_T[tid];
        s_W2[tid] = d_W2[tid];
        s_W2[tid + 128] = d_W2[tid + 128];
        s_W2[tid + 256] = d_W2[tid + 256];
    }

    // stage A: this thread's sample -> row tid, x = [text(16) | image(48)], hi/lo bf16, SW128
    {
        float xv[64];
        const float4* tp = (const float4*)(text + (size_t)gb * 16);
        #pragma unroll
        for (int i = 0; i < 4; i++) {
            float4 v = tp[i];
            xv[4*i+0] = v.x; xv[4*i+1] = v.y; xv[4*i+2] = v.z; xv[4*i+3] = v.w;
        }
        const float4* ip = (const float4*)(image + (size_t)gb * 48);
        #pragma unroll
        for (int i = 0; i < 12; i++) {
            float4 v = ip[i];
            xv[16+4*i+0] = v.x; xv[16+4*i+1] = v.y; xv[16+4*i+2] = v.z; xv[16+4*i+3] = v.w;
        }
        #pragma unroll
        for (int i = 0; i < 8; i++) {   // 8 bf16 = 16B per store
            uint32_t hw[4], lw[4];
            #pragma unroll
            for (int p = 0; p < 4; p++) {
                float x0 = xv[8*i + 2*p], x1 = xv[8*i + 2*p + 1];
                __nv_bfloat162 hv, lv;
                hv.x = __float2bfloat16(x0); hv.y = __float2bfloat16(x1);
                lv.x = __float2bfloat16(x0 - __bfloat162float(hv.x));
                lv.y = __float2bfloat16(x1 - __bfloat162float(hv.y));
                hw[p] = *(uint32_t*)&hv;
                lw[p] = *(uint32_t*)&lv;
            }
            uint32_t sw = sw128((uint32_t)(tid * 128 + i * 16));
            *(uint4*)(sAhi + sw) = make_uint4(hw[0], hw[1], hw[2], hw[3]);
            *(uint4*)(sAlo + sw) = make_uint4(lw[0], lw[1], lw[2], lw[3]);
        }
    }
    __syncthreads();

    uint32_t sbAhi = smem_u32(sAhi), sbAlo = smem_u32(sAlo);
    int lrow = (lane & 7) + ((lane >> 3) & 1) * 8;
    int lcol = ((lane >> 4) & 1) * 16;
    int warpRow = wid * 32;

    // hoisted A fragments: full K for this warp's 32 rows (hi + lo)
    uint32_t ah[2][4][4], al[2][4][4];
    #pragma unroll
    for (int c = 0; c < 4; c++) {
        #pragma unroll
        for (int m = 0; m < 2; m++) {
            uint32_t sw = sw128((uint32_t)((warpRow + m * 16 + lrow) * 128 + c * 32 + lcol));
            LDM_X4(ah[m][c], sbAhi + sw);
            LDM_X4(al[m][c], sbAlo + sw);
        }
    }

    float fp[2][2][4];
    #pragma unroll
    for (int m = 0; m < 2; m++)
        #pragma unroll
        for (int h = 0; h < 2; h++)
            #pragma unroll
            for (int j = 0; j < 4; j++) fp[m][h][j] = 0.f;

    #pragma unroll
    for (int nc = 0; nc < 3; nc++) {
        float C[2][4][4];
        #pragma unroll
        for (int m = 0; m < 2; m++)
            #pragma unroll
            for (int tt = 0; tt < 4; tt++)
                #pragma unroll
                for (int e = 0; e < 4; e++) C[m][tt][e] = 0.f;

        #pragma unroll
        for (int c = 0; c < 4; c++) {
            #pragma unroll
            for (int tt = 0; tt < 4; tt++) {
                int fi = ((nc * 4 + tt) * 4 + c) * 32 + lane;
                uint2 bh = d_Bfrag[fi];
                uint2 bl = d_Bfrag[1536 + fi];
                #pragma unroll
                for (int m = 0; m < 2; m++) {
                    MMA_BF16(C[m][tt], ah[m][c], bh);
                    MMA_BF16(C[m][tt], al[m][c], bh);
                    MMA_BF16(C[m][tt], ah[m][c], bl);
                }
            }
        }
        // fragment epilogue: bias + relu + layer-2 partials
        #pragma unroll
        for (int tt = 0; tt < 4; tt++) {
            int n0 = nc * 32 + tt * 8 + t4 * 2;
            float2 bs = *(const float2*)&s_bias[n0];
            float4 w0 = *(const float4*)&s_W2[n0 * 4];
            float4 w1 = *(const float4*)&s_W2[(n0 + 1) * 4];
            #pragma unroll
            for (int m = 0; m < 2; m++) {
                float h0 = fmaxf(C[m][tt][0] + bs.x, 0.f);   // row g,   col n0
                float h1 = fmaxf(C[m][tt][1] + bs.y, 0.f);   // row g,   col n0+1
                float h2 = fmaxf(C[m][tt][2] + bs.x, 0.f);   // row g+8, col n0
                float h3 = fmaxf(C[m][tt][3] + bs.y, 0.f);   // row g+8, col n0+1
                fp[m][0][0] = fmaf(h0, w0.x, fmaf(h1, w1.x, fp[m][0][0]));
                fp[m][0][1] = fmaf(h0, w0.y, fmaf(h1, w1.y, fp[m][0][1]));
                fp[m][0][2] = fmaf(h0, w0.z, fmaf(h1, w1.z, fp[m][0][2]));
                fp[m][0][3] = fmaf(h0, w0.w, fmaf(h1, w1.w, fp[m][0][3]));
                fp[m][1][0] = fmaf(h2, w0.x, fmaf(h3, w1.x, fp[m][1][0]));
                fp[m][1][1] = fmaf(h2, w0.y, fmaf(h3, w1.y, fp[m][1][1]));
                fp[m][1][2] = fmaf(h2, w0.z, fmaf(h3, w1.z, fp[m][1][2]));
                fp[m][1][3] = fmaf(h2, w0.w, fmaf(h3, w1.w, fp[m][1][3]));
            }
        }
    }

    // quad reduction (lanes 4g..4g+3 hold the same rows, different col ranges)
    #pragma unroll
    for (int m = 0; m < 2; m++)
        #pragma unroll
        for (int h = 0; h < 2; h++)
            #pragma unroll
            for (int j = 0; j < 4; j++) {
                float v = fp[m][h][j];
                v += __shfl_xor_sync(0xffffffffu, v, 1);
                v += __shfl_xor_sync(0xffffffffu, v, 2);
                fp[m][h][j] = v;
            }

    // each quad lane takes one of the 4 rows
    int sel = t4;
    float fa[4];
    #pragma unroll
    for (int j = 0; j < 4; j++) {
        float v0 = (sel & 1) ? fp[0][1][j] : fp[0][0][j];
        float v1 = (sel & 1) ? fp[1][1][j] : fp[1][0][j];
        fa[j] = ((sel >> 1) ? v1 : v0) + s_cls[66 + j];
    }
    int rowLocal = warpRow + ((sel >> 1) << 4) + ((sel & 1) << 3) + g;

    // quantum: full angle f = 0.5*feats_sum; q = T contraction
    float ca[4], sa[4];
    #pragma unroll
    for (int i = 0; i < 4; i++) __sincosf(0.5f * fa[i], &sa[i], &ca[i]);
    float Bv[9] = {1.f, ca[1], sa[1], ca[0], ca[0]*ca[1], ca[0]*sa[1], sa[0], sa[0]*ca[1], sa[0]*sa[1]};
    float q = 0.f;
    #pragma unroll
    for (int n = 0; n < 9; n++) {
        float s2 = 0.f;
        #pragma unroll
        for (int w2 = 0; w2 < 3; w2++) {
            float4 tr = *(const float4*)&s_T[(n * 3 + w2) * 4];
            float dd = fmaf(tr.z, sa[3], fmaf(tr.y, ca[3], tr.x));
            float u2 = (w2 == 0) ? 1.f : (w2 == 1) ? ca[2] : sa[2];
            s2 = fmaf(u2, dd, s2);
        }
        q = fmaf(Bv[n], s2, q);
    }

    // classifier
    float o0 = s_cls[64], o1 = s_cls[65];
    #pragma unroll
    for (int m = 0; m < 16; m++) {
        float h = fmaxf(fmaf(q, s_cls[m], s_cls[16 + m]), 0.f);
        o0 = fmaf(h, s_cls[32 + 2*m], o0);
        o1 = fmaf(h, s_cls[32 + 2*m + 1], o1);
    }
    ((float2*)out)[blockIdx.x * TILE_M + rowLocal] = make_float2(o0, o1);
}

extern "C" void kernel_launch(void* const* d_in, const int* in_sizes, int n_in,
                              void* d_out, int out_size) {
    const float* text = (const float*)d_in[0];
    const float* image = (const float*)d_in[1];
    const float* tW1 = (const float*)d_in[2];
    const float* tb1 = (const float*)d_in[3];
    const float* tW2 = (const float*)d_in[4];
    const float* tb2 = (const float*)d_in[5];
    const float* iW1 = (const float*)d_in[6];
    const float* ib1 = (const float*)d_in[7];
    const float* iW2 = (const float*)d_in[8];
    const float* ib2 = (const float*)d_in[9];
    const float* qweights = (const float*)d_in[10];
    const float* cW1 = (const float*)d_in[11];
    const float* cb1 = (const float*)d_in[12];
    const float* cW2 = (const float*)d_in[13];
    const float* cb2 = (const float*)d_in[14];
    float* out = (float*)d_out;

    int B = in_sizes[0] / 16;  // 524288
    qnn_setup_kernel<<<2, 256>>>(qweights, tW1, tb1, tW2, tb2, iW1, ib1, iW2, ib2);
    qnn_mma_kernel<<<B / TILE_M, NT>>>(text, image, cW1, cb1, cW2, cb2, out);
}